// round 1
// baseline (speedup 1.0000x reference)
#include <cuda_runtime.h>
#include <math.h>

#define BB 8
#define TT 1024
#define DD 1024
#define HH 16
#define HS 64
#define NE 8
#define NTOK (BB*TT)        // 8192
#define DFF 4096
#define LN_EPS 1e-5f

// ---------------- scratch (device globals; no runtime allocation) ----------------
__device__ float g_q[(size_t)BB*HH*TT*HS];
__device__ float g_k[(size_t)BB*HH*TT*HS];
__device__ float g_v[(size_t)BB*HH*TT*HS];
__device__ float g_attn[(size_t)NTOK*DD];
__device__ float g_h[(size_t)NTOK*2*DFF];     // pair-indexed rows: rowid = tok*2 + slot
__device__ float g_y[(size_t)NTOK*2*DD];
__device__ float g_wtok[NTOK*2];
__device__ int   g_rows[NE*NTOK];
__device__ int   g_cnt[NE];

// ---------------- utility ----------------
__global__ void zero_counts_kernel() {
    if (threadIdx.x < NE) g_cnt[threadIdx.x] = 0;
}

// ---------------- QKV projection GEMM ----------------
// grid (NTOK/128, 48), block 256. blockIdx.y: part = y>>4 (0=q,1=k,2=v), h = y&15.
__global__ __launch_bounds__(256) void qkv_gemm_kernel(
    const float* __restrict__ X,
    const float* __restrict__ Wq,
    const float* __restrict__ Wk,
    const float* __restrict__ Wv)
{
    __shared__ float As[16][128];
    __shared__ float Bs[16][64];

    int by = blockIdx.y;
    int part = by >> 4;
    int h = by & 15;
    const float* W = (part == 0) ? Wq : (part == 1) ? Wk : Wv;
    float* Out = (part == 0) ? g_q : (part == 1) ? g_k : g_v;

    int row0 = blockIdx.x * 128;
    int tid = threadIdx.x;
    int tx = tid & 15, ty = tid >> 4;

    float acc[8][4];
#pragma unroll
    for (int i = 0; i < 8; i++)
#pragma unroll
        for (int j = 0; j < 4; j++) acc[i][j] = 0.f;

    for (int k0 = 0; k0 < DD; k0 += 16) {
        {
            int kk = tid & 15, mb = tid >> 4;
#pragma unroll
            for (int i = 0; i < 8; i++) {
                int m = mb + i * 16;
                As[kk][m] = X[(size_t)(row0 + m) * DD + k0 + kk];
            }
        }
        {
            int e = tid & 63, kb = tid >> 6;
#pragma unroll
            for (int i = 0; i < 4; i++) {
                int kk = kb + i * 4;
                Bs[kk][e] = W[((size_t)h * DD + k0 + kk) * HS + e];
            }
        }
        __syncthreads();
#pragma unroll
        for (int kk = 0; kk < 16; kk++) {
            float4 a0 = *(const float4*)&As[kk][ty * 8];
            float4 a1 = *(const float4*)&As[kk][ty * 8 + 4];
            float4 b0 = *(const float4*)&Bs[kk][tx * 4];
            float a[8] = {a0.x, a0.y, a0.z, a0.w, a1.x, a1.y, a1.z, a1.w};
            float b[4] = {b0.x, b0.y, b0.z, b0.w};
#pragma unroll
            for (int i = 0; i < 8; i++)
#pragma unroll
                for (int j = 0; j < 4; j++) acc[i][j] += a[i] * b[j];
        }
        __syncthreads();
    }

#pragma unroll
    for (int i = 0; i < 8; i++) {
        int row = row0 + ty * 8 + i;
        int b = row >> 10, t = row & 1023;
        float* dst = Out + (((size_t)b * HH + h) * TT + t) * HS + tx * 4;
        float4 v4 = make_float4(acc[i][0], acc[i][1], acc[i][2], acc[i][3]);
        *(float4*)dst = v4;
    }
}

// ---------------- causal flash attention ----------------
// grid (16, 128), block 64. Each thread owns one query row.
__global__ __launch_bounds__(64) void attn_kernel()
{
    __shared__ float Ks[64][64];
    __shared__ float Vs[64][64];
    __shared__ float Ss[64][64];   // Ss[kk][tid]

    int bh = blockIdx.y;
    int qt = blockIdx.x;
    int tid = threadIdx.x;
    int row = qt * 64 + tid;

    const float* qp = g_q + ((size_t)bh * TT + row) * HS;
    float q[64];
#pragma unroll
    for (int d4 = 0; d4 < 16; d4++) {
        float4 f = ((const float4*)qp)[d4];
        q[d4 * 4 + 0] = f.x; q[d4 * 4 + 1] = f.y;
        q[d4 * 4 + 2] = f.z; q[d4 * 4 + 3] = f.w;
    }
    float acc[64];
#pragma unroll
    for (int d = 0; d < 64; d++) acc[d] = 0.f;
    float mval = -INFINITY, l = 0.f;

    for (int kt = 0; kt <= qt; kt++) {
        int k0 = kt * 64;
        const float* kp = g_k + ((size_t)bh * TT + k0) * HS;
        const float* vp = g_v + ((size_t)bh * TT + k0) * HS;
        __syncthreads();
#pragma unroll
        for (int i = 0; i < 16; i++) {
            int idx = tid + i * 64;
            int r = idx >> 4, c4 = idx & 15;
            ((float4*)Ks[r])[c4] = ((const float4*)(kp + (size_t)r * HS))[c4];
            ((float4*)Vs[r])[c4] = ((const float4*)(vp + (size_t)r * HS))[c4];
        }
        __syncthreads();

        int kmax = (kt == qt) ? (tid + 1) : 64;
        float tmax = -INFINITY;
        for (int kk = 0; kk < kmax; kk++) {
            const float4* kr = (const float4*)Ks[kk];
            float s0 = 0.f, s1 = 0.f, s2 = 0.f, s3 = 0.f;
#pragma unroll
            for (int d4 = 0; d4 < 16; d4++) {
                float4 kv = kr[d4];
                s0 += q[d4 * 4 + 0] * kv.x;
                s1 += q[d4 * 4 + 1] * kv.y;
                s2 += q[d4 * 4 + 2] * kv.z;
                s3 += q[d4 * 4 + 3] * kv.w;
            }
            float ss = ((s0 + s1) + (s2 + s3)) * 0.03125f;
            Ss[kk][tid] = ss;
            tmax = fmaxf(tmax, ss);
        }
        float mnew = fmaxf(mval, tmax);
        float corr = __expf(mval - mnew);
        l *= corr;
#pragma unroll
        for (int d = 0; d < 64; d++) acc[d] *= corr;
        for (int kk = 0; kk < kmax; kk++) {
            float p = __expf(Ss[kk][tid] - mnew);
            l += p;
            const float4* vr = (const float4*)Vs[kk];
#pragma unroll
            for (int d4 = 0; d4 < 16; d4++) {
                float4 vv = vr[d4];
                acc[d4 * 4 + 0] += p * vv.x;
                acc[d4 * 4 + 1] += p * vv.y;
                acc[d4 * 4 + 2] += p * vv.z;
                acc[d4 * 4 + 3] += p * vv.w;
            }
        }
        mval = mnew;
    }

    int b = bh >> 4, h = bh & 15;
    float inv = 1.f / l;
    float* op = g_attn + ((size_t)b * TT + row) * DD + h * HS;
#pragma unroll
    for (int d4 = 0; d4 < 16; d4++) {
        float4 v4 = make_float4(acc[d4 * 4 + 0] * inv, acc[d4 * 4 + 1] * inv,
                                acc[d4 * 4 + 2] * inv, acc[d4 * 4 + 3] * inv);
        ((float4*)op)[d4] = v4;
    }
}

// ---------------- MoE routing: gate + top-2 + softmax + expert lists ----------------
// grid (NTOK/8), block 256 (8 warps, one token per warp)
__global__ __launch_bounds__(256) void route_kernel(
    const float* __restrict__ X, const float* __restrict__ Wg)
{
    int tok = (blockIdx.x * blockDim.x + threadIdx.x) >> 5;
    int lane = threadIdx.x & 31;
    if (tok >= NTOK) return;
    const float* xr = X + (size_t)tok * DD;
    float p[NE];
#pragma unroll
    for (int e = 0; e < NE; e++) p[e] = 0.f;
    for (int d = lane; d < DD; d += 32) {
        float xv = xr[d];
#pragma unroll
        for (int e = 0; e < NE; e++) p[e] += xv * Wg[d * NE + e];
    }
#pragma unroll
    for (int e = 0; e < NE; e++)
#pragma unroll
        for (int off = 16; off; off >>= 1)
            p[e] += __shfl_xor_sync(0xffffffffu, p[e], off);

    if (lane == 0) {
        int i0 = 0; float v0 = p[0];
#pragma unroll
        for (int e = 1; e < NE; e++) if (p[e] > v0) { v0 = p[e]; i0 = e; }
        int i1 = -1; float v1 = -INFINITY;
#pragma unroll
        for (int e = 0; e < NE; e++) if (e != i0 && p[e] > v1) { v1 = p[e]; i1 = e; }
        float e1v = expf(v1 - v0);
        float inv = 1.f / (1.f + e1v);
        g_wtok[tok * 2 + 0] = inv;
        g_wtok[tok * 2 + 1] = e1v * inv;
        int pos0 = atomicAdd(&g_cnt[i0], 1);
        g_rows[i0 * NTOK + pos0] = tok * 2;
        int pos1 = atomicAdd(&g_cnt[i1], 1);
        g_rows[i1 * NTOK + pos1] = tok * 2 + 1;
    }
}

// ---------------- MoE expert GEMM 1: h = relu(x @ W1[e] + b1[e]) ----------------
// grid (64, DFF/64, NE), block 256
__global__ __launch_bounds__(256) void moe_gemm1_kernel(
    const float* __restrict__ X,
    const float* __restrict__ W1,
    const float* __restrict__ b1)
{
    int e = blockIdx.z;
    int cnt = g_cnt[e];
    int m0 = blockIdx.x * 128;
    if (m0 >= cnt) return;
    int col0 = blockIdx.y * 64;

    __shared__ float As[16][128];
    __shared__ float Bs[16][64];
    __shared__ int rowids[128];

    int tid = threadIdx.x;
    if (tid < 128) {
        int m = m0 + tid;
        rowids[tid] = (m < cnt) ? g_rows[e * NTOK + m] : -1;
    }
    __syncthreads();

    float acc[8][4];
#pragma unroll
    for (int i = 0; i < 8; i++)
#pragma unroll
        for (int j = 0; j < 4; j++) acc[i][j] = 0.f;

    const float* Wp = W1 + (size_t)e * DD * DFF;
    int tx = tid & 15, ty = tid >> 4;

    for (int k0 = 0; k0 < DD; k0 += 16) {
        {
            int kk = tid & 15, mb = tid >> 4;
#pragma unroll
            for (int i = 0; i < 8; i++) {
                int m = mb + i * 16;
                int rid = rowids[m];
                int tok = (rid >= 0) ? (rid >> 1) : 0;
                As[kk][m] = X[(size_t)tok * DD + k0 + kk];
            }
        }
        {
            int n = tid & 63, kb = tid >> 6;
#pragma unroll
            for (int i = 0; i < 4; i++) {
                int kk = kb + i * 4;
                Bs[kk][n] = Wp[(size_t)(k0 + kk) * DFF + col0 + n];
            }
        }
        __syncthreads();
#pragma unroll
        for (int kk = 0; kk < 16; kk++) {
            float4 a0 = *(const float4*)&As[kk][ty * 8];
            float4 a1 = *(const float4*)&As[kk][ty * 8 + 4];
            float4 b0 = *(const float4*)&Bs[kk][tx * 4];
            float a[8] = {a0.x, a0.y, a0.z, a0.w, a1.x, a1.y, a1.z, a1.w};
            float b[4] = {b0.x, b0.y, b0.z, b0.w};
#pragma unroll
            for (int i = 0; i < 8; i++)
#pragma unroll
                for (int j = 0; j < 4; j++) acc[i][j] += a[i] * b[j];
        }
        __syncthreads();
    }

    float4 bias = *(const float4*)&b1[(size_t)e * DFF + col0 + tx * 4];
#pragma unroll
    for (int i = 0; i < 8; i++) {
        int m = ty * 8 + i;
        int rid = rowids[m];
        if (rid < 0) continue;
        float* dst = g_h + (size_t)rid * DFF + col0 + tx * 4;
        float4 v4 = make_float4(fmaxf(acc[i][0] + bias.x, 0.f),
                                fmaxf(acc[i][1] + bias.y, 0.f),
                                fmaxf(acc[i][2] + bias.z, 0.f),
                                fmaxf(acc[i][3] + bias.w, 0.f));
        *(float4*)dst = v4;
    }
}

// ---------------- MoE expert GEMM 2: y = h @ W2[e] + b2[e] ----------------
// grid (64, DD/64, NE), block 256
__global__ __launch_bounds__(256) void moe_gemm2_kernel(
    const float* __restrict__ W2,
    const float* __restrict__ b2)
{
    int e = blockIdx.z;
    int cnt = g_cnt[e];
    int m0 = blockIdx.x * 128;
    if (m0 >= cnt) return;
    int col0 = blockIdx.y * 64;

    __shared__ float As[16][128];
    __shared__ float Bs[16][64];
    __shared__ int rowids[128];

    int tid = threadIdx.x;
    if (tid < 128) {
        int m = m0 + tid;
        rowids[tid] = (m < cnt) ? g_rows[e * NTOK + m] : -1;
    }
    __syncthreads();

    float acc[8][4];
#pragma unroll
    for (int i = 0; i < 8; i++)
#pragma unroll
        for (int j = 0; j < 4; j++) acc[i][j] = 0.f;

    const float* Wp = W2 + (size_t)e * DFF * DD;
    int tx = tid & 15, ty = tid >> 4;

    for (int k0 = 0; k0 < DFF; k0 += 16) {
        {
            int kk = tid & 15, mb = tid >> 4;
#pragma unroll
            for (int i = 0; i < 8; i++) {
                int m = mb + i * 16;
                int rid = rowids[m];
                size_t rr = (rid >= 0) ? (size_t)rid : 0;
                As[kk][m] = g_h[rr * DFF + k0 + kk];
            }
        }
        {
            int n = tid & 63, kb = tid >> 6;
#pragma unroll
            for (int i = 0; i < 4; i++) {
                int kk = kb + i * 4;
                Bs[kk][n] = Wp[(size_t)(k0 + kk) * DD + col0 + n];
            }
        }
        __syncthreads();
#pragma unroll
        for (int kk = 0; kk < 16; kk++) {
            float4 a0 = *(const float4*)&As[kk][ty * 8];
            float4 a1 = *(const float4*)&As[kk][ty * 8 + 4];
            float4 b0 = *(const float4*)&Bs[kk][tx * 4];
            float a[8] = {a0.x, a0.y, a0.z, a0.w, a1.x, a1.y, a1.z, a1.w};
            float b[4] = {b0.x, b0.y, b0.z, b0.w};
#pragma unroll
            for (int i = 0; i < 8; i++)
#pragma unroll
                for (int j = 0; j < 4; j++) acc[i][j] += a[i] * b[j];
        }
        __syncthreads();
    }

    float4 bias = *(const float4*)&b2[(size_t)e * DD + col0 + tx * 4];
#pragma unroll
    for (int i = 0; i < 8; i++) {
        int m = ty * 8 + i;
        int rid = rowids[m];
        if (rid < 0) continue;
        float* dst = g_y + (size_t)rid * DD + col0 + tx * 4;
        float4 v4 = make_float4(acc[i][0] + bias.x, acc[i][1] + bias.y,
                                acc[i][2] + bias.z, acc[i][3] + bias.w);
        *(float4*)dst = v4;
    }
}

// ---------------- final: out = x + LN(attn)*g1+be1 + LN(moe)*g2+be2 ----------------
__device__ __forceinline__ float4 block_reduce4(float4 v) {
    __shared__ float4 sh[8];
    __shared__ float4 bc;
    int lane = threadIdx.x & 31, w = threadIdx.x >> 5;
#pragma unroll
    for (int off = 16; off; off >>= 1) {
        v.x += __shfl_xor_sync(0xffffffffu, v.x, off);
        v.y += __shfl_xor_sync(0xffffffffu, v.y, off);
        v.z += __shfl_xor_sync(0xffffffffu, v.z, off);
        v.w += __shfl_xor_sync(0xffffffffu, v.w, off);
    }
    if (lane == 0) sh[w] = v;
    __syncthreads();
    if (w == 0) {
        float4 t = (lane < 8) ? sh[lane] : make_float4(0, 0, 0, 0);
#pragma unroll
        for (int off = 4; off; off >>= 1) {
            t.x += __shfl_xor_sync(0xffffffffu, t.x, off);
            t.y += __shfl_xor_sync(0xffffffffu, t.y, off);
            t.z += __shfl_xor_sync(0xffffffffu, t.z, off);
            t.w += __shfl_xor_sync(0xffffffffu, t.w, off);
        }
        if (lane == 0) bc = t;
    }
    __syncthreads();
    return bc;
}

// grid (NTOK), block 256
__global__ __launch_bounds__(256) void final_kernel(
    const float* __restrict__ X,
    const float* __restrict__ g1, const float* __restrict__ be1,
    const float* __restrict__ g2, const float* __restrict__ be2,
    float* __restrict__ out)
{
    int t = blockIdx.x;
    int tid = threadIdx.x;
    const float* ar = g_attn + (size_t)t * DD;
    const float* y0 = g_y + (size_t)(t * 2) * DD;
    const float* y1 = g_y + (size_t)(t * 2 + 1) * DD;
    float w0 = g_wtok[t * 2], w1 = g_wtok[t * 2 + 1];

    float4 a4 = ((const float4*)ar)[tid];
    float4 y04 = ((const float4*)y0)[tid];
    float4 y14 = ((const float4*)y1)[tid];
    float a[4] = {a4.x, a4.y, a4.z, a4.w};
    float m[4] = {w0 * y04.x + w1 * y14.x, w0 * y04.y + w1 * y14.y,
                  w0 * y04.z + w1 * y14.z, w0 * y04.w + w1 * y14.w};

    float4 s = make_float4(0, 0, 0, 0);  // sa, sa2, sm, sm2
#pragma unroll
    for (int j = 0; j < 4; j++) {
        s.x += a[j]; s.y += a[j] * a[j];
        s.z += m[j]; s.w += m[j] * m[j];
    }
    s = block_reduce4(s);
    const float invD = 1.0f / (float)DD;
    float mua = s.x * invD;
    float vara = fmaxf(s.y * invD - mua * mua, 0.f);
    float rsa = rsqrtf(vara + LN_EPS);
    float mum = s.z * invD;
    float varm = fmaxf(s.w * invD - mum * mum, 0.f);
    float rsm = rsqrtf(varm + LN_EPS);

    float4 x4 = ((const float4*)(X + (size_t)t * DD))[tid];
    float4 g14 = ((const float4*)g1)[tid];
    float4 b14 = ((const float4*)be1)[tid];
    float4 g24 = ((const float4*)g2)[tid];
    float4 b24 = ((const float4*)be2)[tid];
    float xs[4] = {x4.x, x4.y, x4.z, x4.w};
    float g1s[4] = {g14.x, g14.y, g14.z, g14.w};
    float b1s[4] = {b14.x, b14.y, b14.z, b14.w};
    float g2s[4] = {g24.x, g24.y, g24.z, g24.w};
    float b2s[4] = {b24.x, b24.y, b24.z, b24.w};
    float o[4];
#pragma unroll
    for (int j = 0; j < 4; j++) {
        o[j] = xs[j]
             + (a[j] - mua) * rsa * g1s[j] + b1s[j]
             + (m[j] - mum) * rsm * g2s[j] + b2s[j];
    }
    ((float4*)(out + (size_t)t * DD))[tid] = make_float4(o[0], o[1], o[2], o[3]);
}

// ---------------- launch ----------------
extern "C" void kernel_launch(void* const* d_in, const int* in_sizes, int n_in,
                              void* d_out, int out_size)
{
    const float* x   = (const float*)d_in[0];
    const float* Wq  = (const float*)d_in[1];
    const float* Wk  = (const float*)d_in[2];
    const float* Wv  = (const float*)d_in[3];
    const float* Wg  = (const float*)d_in[4];
    const float* W1  = (const float*)d_in[5];
    const float* b1  = (const float*)d_in[6];
    const float* W2  = (const float*)d_in[7];
    const float* b2  = (const float*)d_in[8];
    const float* g1  = (const float*)d_in[9];
    const float* be1 = (const float*)d_in[10];
    const float* g2  = (const float*)d_in[11];
    const float* be2 = (const float*)d_in[12];
    float* out = (float*)d_out;

    zero_counts_kernel<<<1, 32>>>();
    qkv_gemm_kernel<<<dim3(NTOK / 128, 48), 256>>>(x, Wq, Wk, Wv);
    attn_kernel<<<dim3(16, BB * HH), 64>>>();
    route_kernel<<<NTOK / 8, 256>>>(x, Wg);
    moe_gemm1_kernel<<<dim3(64, DFF / 64, NE), 256>>>(x, W1, b1);
    moe_gemm2_kernel<<<dim3(64, DD / 64, NE), 256>>>(W2, b2);
    final_kernel<<<NTOK, 256>>>(x, g1, be1, g2, be2, out);
}